// round 13
// baseline (speedup 1.0000x reference)
#include <cuda_runtime.h>
#include <math.h>

#define Vv      40
#define Ee      512
#define Hh      512
#define DKk     512
#define DVv     512
#define TENC    8192
#define MAXLEN  200
#define EOSI    38
#define SCALE   0.04419417382415922f   /* 1/sqrt(512) */

#define NB      128          /* worker blocks: 64 keys, 4 gh-rows each */
#define TPB     1024
#define ROWS_PB 4
#define KEYS_PB 64
#define NCPY    16           /* broadcast replication */

// -------- persistent device scratch --------
__device__ float  g_GIT[Vv*3*Hh];                    // [best][1536]
__device__ float  g_WV[TENC*Vv];                     // values @ w_out[:, :512]^T
__device__ __align__(16) float4 g_hT4R[NCPY][Hh/2];  // 16 copies {h2i,tag,h2i+1,tag}
__device__ __align__(16) float2 g_pUT[(Vv+1)*NB];    // rows 0..39 pU, row 40 denom {val,tag}
__device__ __align__(16) float2 g_pOHT[Vv];          // {w_out[:,512:]@h row, tag}
__device__ __align__(16) float2 g_ghT[3*Hh];         // {w_hh@h row-gate, tag}, idx row*3+gate
__device__ __align__(16) float4 g_verdR[NCPY*8];     // 16 copies 128B apart {best,inv,tag,0}

// -------- weak L2-direct vector ops --------
__device__ __forceinline__ float2 ldcg2(const float2* p) {
    float2 v;
    asm volatile("ld.global.cg.v2.f32 {%0,%1},[%2];"
                 : "=f"(v.x), "=f"(v.y) : "l"(p) : "memory");
    return v;
}
__device__ __forceinline__ float4 ldcg4(const float4* p) {
    float4 v;
    asm volatile("ld.global.cg.v4.f32 {%0,%1,%2,%3},[%4];"
                 : "=f"(v.x), "=f"(v.y), "=f"(v.z), "=f"(v.w) : "l"(p) : "memory");
    return v;
}
__device__ __forceinline__ void stcg2(float2* p, float2 v) {
    asm volatile("st.global.cg.v2.f32 [%0],{%1,%2};"
                 :: "l"(p), "f"(v.x), "f"(v.y) : "memory");
}
__device__ __forceinline__ void stcg4(float4* p, float4 v) {
    asm volatile("st.global.cg.v4.f32 [%0],{%1,%2,%3,%4};"
                 :: "l"(p), "f"(v.x), "f"(v.y), "f"(v.z), "f"(v.w) : "memory");
}

// -------- reset tags every launch (graph-replay safe) --------
__global__ void reset_kernel()
{
    int tid = threadIdx.x;
    for (int i = tid; i < (Vv+1)*NB; i += blockDim.x) g_pUT[i] = make_float2(0.f, 0.f);
    for (int i = tid; i < NCPY*Hh/2; i += blockDim.x)
        ((float4*)g_hT4R)[i] = make_float4(0.f,0.f,0.f,0.f);
    for (int i = tid; i < 3*Hh; i += blockDim.x) g_ghT[i] = make_float2(0.f, 0.f);
    if (tid < Vv) g_pOHT[tid] = make_float2(0.f, 0.f);
    for (int i = tid; i < NCPY*8; i += blockDim.x) g_verdR[i] = make_float4(0.f,0.f,0.f,0.f);
}

// -------- GIT[v][gid] = dot(w_ih[gid], embed[v]) + b_ih[gid] ----------------
__global__ void gi_kernel(const float* __restrict__ w_ih,
                          const float* __restrict__ b_ih,
                          const float* __restrict__ embed)
{
    extern __shared__ float sE[];
    for (int i = threadIdx.x; i < Vv*Ee; i += blockDim.x) sE[i] = embed[i];
    __syncthreads();

    int lane = threadIdx.x & 31;
    int gid  = blockIdx.x * (blockDim.x >> 5) + (threadIdx.x >> 5);
    if (gid >= 3*Hh) return;

    float4 wreg[4];
    const float4* wr = (const float4*)(w_ih + (size_t)gid * Ee);
    #pragma unroll
    for (int j = 0; j < 4; ++j) wreg[j] = wr[lane + 32*j];
    float bb = b_ih[gid];

    for (int v = 0; v < Vv; ++v) {
        const float4* ev = (const float4*)(sE + v*Ee);
        float a = 0.f;
        #pragma unroll
        for (int j = 0; j < 4; ++j) {
            float4 e = ev[lane + 32*j];
            a = fmaf(wreg[j].x, e.x, a); a = fmaf(wreg[j].y, e.y, a);
            a = fmaf(wreg[j].z, e.z, a); a = fmaf(wreg[j].w, e.w, a);
        }
        #pragma unroll
        for (int o = 16; o > 0; o >>= 1) a += __shfl_down_sync(0xffffffffu, a, o);
        if (lane == 0) g_GIT[(size_t)v*(3*Hh) + gid] = a + bb;
    }
}

// -------- WV[t][k] = dot(values[t], w_out[k][0:512]) ------------------------
__global__ void wv_kernel(const float* __restrict__ enc,
                          const float* __restrict__ w_out)
{
    extern __shared__ float sW[];
    for (int i = threadIdx.x; i < Vv*DVv; i += blockDim.x) {
        int k = i / DVv, j = i % DVv;
        sW[i] = w_out[(size_t)k*(DVv+Hh) + j];
    }
    __syncthreads();

    int lane  = threadIdx.x & 31;
    int gw    = blockIdx.x * (blockDim.x >> 5) + (threadIdx.x >> 5);
    int wspan = gridDim.x  * (blockDim.x >> 5);

    for (int t = gw; t < TENC; t += wspan) {
        float4 vreg[4];
        const float4* vr = (const float4*)(enc + (size_t)t*(DKk+DVv) + DKk);
        #pragma unroll
        for (int j = 0; j < 4; ++j) vreg[j] = vr[lane + 32*j];
        for (int k = 0; k < Vv; ++k) {
            const float4* wk = (const float4*)(sW + k*DVv);
            float a = 0.f;
            #pragma unroll
            for (int j = 0; j < 4; ++j) {
                float4 w = wk[lane + 32*j];
                a = fmaf(vreg[j].x, w.x, a); a = fmaf(vreg[j].y, w.y, a);
                a = fmaf(vreg[j].z, w.z, a); a = fmaf(vreg[j].w, w.w, a);
            }
            #pragma unroll
            for (int o = 16; o > 0; o >>= 1) a += __shfl_down_sync(0xffffffffu, a, o);
            if (lane == 0) g_WV[(size_t)t*Vv + k] = a;
        }
    }
}

// -------- persistent decoder: 128 workers + 1 dedicated reducer -------------
__global__ void __launch_bounds__(TPB, 1)
dec_main(const float* __restrict__ enc,
         const float* __restrict__ hidden,
         const float* __restrict__ w_hh,
         const float* __restrict__ b_hh,
         const float* __restrict__ w_out,
         const float* __restrict__ b_out,
         float*       __restrict__ dout)
{
    __shared__ float  h_sh[Hh];
    __shared__ float  h_stage[Hh];
    __shared__ float  sGH[ROWS_PB][3];
    __shared__ float  sU[32][41];
    __shared__ float  sDen[32];
    __shared__ float  sRR[Vv+1][16];
    __shared__ float  sOH[Vv];
    __shared__ float  sGHall[3*Hh];
    __shared__ float4 s_vd;
    __shared__ int    s_bi;
    __shared__ float  s_inv;

    const int tid  = threadIdx.x;
    const int wid  = tid >> 5;
    const int lane = tid & 31;
    const int b    = blockIdx.x;

    float* attn = dout + (MAXLEN*Vv + 1);

    // ========================= DEDICATED REDUCER =========================
    if (b == NB) {
        // h(0) poll (tag 1), done-cached
        {
            int done = (tid < Hh/2) ? 0 : 1;
            for (;;) {
                if (!done) {
                    float4 hv = ldcg4(&g_hT4R[0][tid]);
                    if (hv.y >= 1.f && hv.w >= 1.f) {
                        h_sh[2*tid] = hv.x; h_sh[2*tid + 1] = hv.z;
                        done = 1;
                    }
                }
                if (__syncthreads_and(done)) break;
            }
        }

        int mylen = MAXLEN;
        for (int s = 0; s < MAXLEN; ++s) {
            const float tagf = (float)(s + 1);
            const int r = tid >> 4, j = tid & 15;

            // ---- loop1: partials + pOHT, done-cached ----
            {
                int done = (tid < 656 || (tid >= 784 && tid < 784 + Vv)) ? 0 : 1;
                for (;;) {
                    if (!done) {
                        if (tid < 656) {
                            const float4* base = (const float4*)g_pUT + r*(NB/2);
                            float4 a0 = ldcg4(base + j);
                            float4 a1 = ldcg4(base + j + 16);
                            float4 a2 = ldcg4(base + j + 32);
                            float4 a3 = ldcg4(base + j + 48);
                            if (a0.y >= tagf && a0.w >= tagf && a1.y >= tagf && a1.w >= tagf &&
                                a2.y >= tagf && a2.w >= tagf && a3.y >= tagf && a3.w >= tagf) {
                                sRR[r][j] = (a0.x + a0.z) + (a1.x + a1.z)
                                          + (a2.x + a2.z) + (a3.x + a3.z);
                                done = 1;
                            }
                        } else {
                            float2 e = ldcg2(&g_pOHT[tid - 784]);
                            if (e.y >= tagf) { sOH[tid - 784] = e.x; done = 1; }
                        }
                    }
                    if (__syncthreads_and(done)) break;
                }
            }

            // ---- warp 0: denom, logits, argmax (dout stores deferred) ----
            float v1 = 0.f, v2 = -3.4e38f;
            if (wid == 0) {
                float d = 0.f;
                #pragma unroll
                for (int q = 0; q < 16; ++q) d += sRR[Vv][q];
                float inv = 1.0f / d;

                int k1 = lane, k2 = lane + 32;
                {
                    float a = 0.f;
                    #pragma unroll
                    for (int q = 0; q < 16; ++q) a += sRR[k1][q];
                    v1 = a*inv + sOH[k1] + b_out[k1];
                }
                if (lane < Vv - 32) {
                    float a = 0.f;
                    #pragma unroll
                    for (int q = 0; q < 16; ++q) a += sRR[k2][q];
                    v2 = a*inv + sOH[k2] + b_out[k2];
                }
                float bv; int bi;
                if (v2 > v1) { bv = v2; bi = k2; } else { bv = v1; bi = k1; }
                #pragma unroll
                for (int o = 16; o > 0; o >>= 1) {
                    float ov = __shfl_xor_sync(0xffffffffu, bv, o);
                    int   oi = __shfl_xor_sync(0xffffffffu, bi, o);
                    if (ov > bv || (ov == bv && oi < bi)) { bv = ov; bi = oi; }
                }
                if (lane == 0) { s_bi = bi; s_inv = inv; }
            }

            // ---- loop2: gh, done-cached (usually already arrived) ----
            {
                int done = (tid < 3*Hh/2) ? 0 : 1;
                for (;;) {
                    if (!done) {
                        float4 e = ldcg4(((const float4*)g_ghT) + tid);
                        if (e.y >= tagf && e.w >= tagf) {
                            sGHall[2*tid] = e.x; sGHall[2*tid + 1] = e.z;
                            done = 1;
                        }
                    }
                    if (__syncthreads_and(done)) break;
                }
            }

            // ---- full 512-row combine -> h_stage ----
            if (tid < Hh) {
                int row = tid;
                const float* git = g_GIT + (size_t)s_bi * (3*Hh);
                float ghr = sGHall[3*row    ] + b_hh[row];
                float ghz = sGHall[3*row + 1] + b_hh[Hh + row];
                float ghn = sGHall[3*row + 2] + b_hh[2*Hh + row];
                float gir = git[row], giz = git[Hh + row], gin = git[2*Hh + row];
                float rr = 1.f/(1.f + __expf(-(gir + ghr)));
                float zz = 1.f/(1.f + __expf(-(giz + ghz)));
                float x  = gin + rr*ghn;
                float ex = __expf(2.f*x);
                float nn = (ex - 1.f)/(ex + 1.f);
                h_stage[row] = (1.f - zz)*nn + zz*h_sh[row];
            }
            __syncthreads();

            // ---- publish h(s+1) tag s+2 to all copies + verdict(s) tag s+1 ----
            if (tid < Hh/2) {
                float4 pk = make_float4(h_stage[2*tid], tagf + 1.f,
                                        h_stage[2*tid + 1], tagf + 1.f);
                #pragma unroll
                for (int c = 0; c < NCPY; ++c) stcg4(&g_hT4R[c][tid], pk);
            }
            if (wid == 16 && lane < NCPY)
                stcg4(&g_verdR[lane*8], make_float4((float)s_bi, s_inv, tagf, 0.f));

            // ---- off critical path: dout logits, lens, h_sh update ----
            if (wid == 0) {
                dout[s*Vv + lane] = v1;
                if (lane < Vv - 32) dout[s*Vv + lane + 32] = v2;
                if (lane == 0) {
                    if (s_bi == EOSI && mylen == MAXLEN) mylen = s;
                    if (s == MAXLEN-1) dout[MAXLEN*Vv] = (float)mylen;   // lens
                }
            }
            if (tid < Hh) h_sh[tid] = h_stage[tid];   // same-thread RW across barriers
        }
        return;
    }

    // ========================= WORKER BLOCKS =========================
    const int t0   = b * KEYS_PB;
    const int row0 = b * ROWS_PB;
    float e0 = 0.f, e1 = 0.f;

    #define GH_PUBLISH(TAGF)                                                       \
    do {                                                                           \
        if (wid < 12) {                                                            \
            int rl = wid / 3, gate = wid % 3;                                      \
            const float4* wr = (const float4*)(w_hh +                              \
                               (size_t)(gate*Hh + row0 + rl) * Hh);                \
            const float4* hv4g = (const float4*)h_sh;                              \
            float a = 0.f;                                                         \
            _Pragma("unroll")                                                      \
            for (int j = 0; j < 4; ++j) {                                          \
                float4 w = wr[lane + 32*j], h = hv4g[lane + 32*j];                 \
                a = fmaf(w.x, h.x, a); a = fmaf(w.y, h.y, a);                      \
                a = fmaf(w.z, h.z, a); a = fmaf(w.w, h.w, a);                      \
            }                                                                      \
            _Pragma("unroll")                                                      \
            for (int o = 16; o > 0; o >>= 1) a += __shfl_xor_sync(0xffffffffu, a, o); \
            if (lane == 0)                                                         \
                stcg2(&g_ghT[(row0 + rl)*3 + gate], make_float2(a, (TAGF)));       \
        }                                                                          \
    } while (0)

    // ---- prologue: h(-1)=hidden; gh(hidden) in smem; distributed h(0) ----
    if (tid < Hh/4) ((float4*)h_sh)[tid] = ((const float4*)hidden)[tid];
    __syncthreads();
    if (wid < 12) {
        int rl = wid / 3, gate = wid % 3;
        const float4* wr = (const float4*)(w_hh + (size_t)(gate*Hh + row0 + rl) * Hh);
        const float4* hv4g = (const float4*)h_sh;
        float a = 0.f;
        #pragma unroll
        for (int j = 0; j < 4; ++j) {
            float4 w = wr[lane + 32*j], h = hv4g[lane + 32*j];
            a = fmaf(w.x, h.x, a); a = fmaf(w.y, h.y, a);
            a = fmaf(w.z, h.z, a); a = fmaf(w.w, h.w, a);
        }
        #pragma unroll
        for (int o = 16; o > 0; o >>= 1) a += __shfl_xor_sync(0xffffffffu, a, o);
        if (lane == 0) sGH[rl][gate] = a;
    }
    __syncthreads();
    if (wid == 0) {                              // distributed h(0), tag 1
        float hnv = 0.f;
        if (lane < ROWS_PB) {
            int row = row0 + lane;
            const float* git = g_GIT + (size_t)EOSI * (3*Hh);
            float ghr = sGH[lane][0] + b_hh[row];
            float ghz = sGH[lane][1] + b_hh[Hh + row];
            float ghn = sGH[lane][2] + b_hh[2*Hh + row];
            float gir = git[row], giz = git[Hh + row], gin = git[2*Hh + row];
            float rr = 1.f/(1.f + __expf(-(gir + ghr)));
            float zz = 1.f/(1.f + __expf(-(giz + ghz)));
            float x  = gin + rr*ghn;
            float ex = __expf(2.f*x);
            float nn = (ex - 1.f)/(ex + 1.f);
            hnv = (1.f - zz)*nn + zz*h_sh[row];
        }
        float up = __shfl_down_sync(0xffffffffu, hnv, 1);
        if (lane == 0) {
            float4 pk = make_float4(hnv, 1.f, up, 1.f);
            #pragma unroll
            for (int c = 0; c < NCPY; ++c) stcg4(&g_hT4R[c][2*b], pk);
        }
        if (lane == 2) {
            float4 pk = make_float4(hnv, 1.f, up, 1.f);
            #pragma unroll
            for (int c = 0; c < NCPY; ++c) stcg4(&g_hT4R[c][2*b + 1], pk);
        }
    }

    for (int s = 0; s < MAXLEN; ++s) {
        const float tagf = (float)(s + 1);

        // ---- poll h(s) (tag s+1) + verdict(s-1) (tag s), done-cached ----
        {
            int done = (tid < Hh/2) ? 0 : ((tid == Hh/2 && s > 0) ? 0 : 1);
            for (;;) {
                if (!done) {
                    if (tid < Hh/2) {
                        float4 hv = ldcg4(&g_hT4R[b & (NCPY-1)][tid]);
                        if (hv.y >= tagf && hv.w >= tagf) {
                            h_sh[2*tid] = hv.x; h_sh[2*tid + 1] = hv.z;
                            done = 1;
                        }
                    } else {
                        float4 v = ldcg4(&g_verdR[(b & (NCPY-1))*8]);
                        if (v.z >= (float)s) { s_vd = v; done = 1; }
                    }
                }
                if (__syncthreads_and(done)) break;
            }
        }

        // ---- store normalized attention row (s-1) from registers ----
        if (s > 0 && lane == 0) {
            float inv = s_vd.y;
            attn[(size_t)(s-1)*TENC + t0 + wid     ] = e0 * inv;
            attn[(size_t)(s-1)*TENC + t0 + wid + 32] = e1 * inv;
        }

        // ---- pOutH row (worker blocks 1..40, warp 31) ----
        if (b >= 1 && b <= Vv && wid == 31) {
            int k = b - 1;
            const float4* wr  = (const float4*)(w_out + (size_t)k*(DVv+Hh) + DVv);
            const float4* hv4 = (const float4*)h_sh;
            float acc = 0.f;
            #pragma unroll
            for (int j = 0; j < 4; ++j) {
                float4 w = wr[lane + 32*j], h = hv4[lane + 32*j];
                acc = fmaf(w.x, h.x, acc); acc = fmaf(w.y, h.y, acc);
                acc = fmaf(w.z, h.z, acc); acc = fmaf(w.w, h.w, acc);
            }
            #pragma unroll
            for (int o = 16; o > 0; o >>= 1) acc += __shfl_xor_sync(0xffffffffu, acc, o);
            if (lane == 0) stcg2(&g_pOHT[k], make_float2(acc, tagf));
        }

        // ---- attention over this block's 64 keys (L1-resident) ----
        {
            const float4* hv4 = (const float4*)h_sh;
            float4 h0 = hv4[lane], h1 = hv4[lane+32], h2 = hv4[lane+64], h3 = hv4[lane+96];
            float acc0 = 0.f, acc1 = 0.f, den = 0.f;
            #pragma unroll
            for (int it = 0; it < 2; ++it) {
                int t = t0 + wid + it*32;
                const float4* kr = (const float4*)(enc + (size_t)t*(DKk+DVv));
                float4 k0 = kr[lane], k1 = kr[lane+32], k2 = kr[lane+64], k3 = kr[lane+96];
                float a = 0.f;
                a = fmaf(k0.x, h0.x, a); a = fmaf(k0.y, h0.y, a);
                a = fmaf(k0.z, h0.z, a); a = fmaf(k0.w, h0.w, a);
                a = fmaf(k1.x, h1.x, a); a = fmaf(k1.y, h1.y, a);
                a = fmaf(k1.z, h1.z, a); a = fmaf(k1.w, h1.w, a);
                a = fmaf(k2.x, h2.x, a); a = fmaf(k2.y, h2.y, a);
                a = fmaf(k2.z, h2.z, a); a = fmaf(k2.w, h2.w, a);
                a = fmaf(k3.x, h3.x, a); a = fmaf(k3.y, h3.y, a);
                a = fmaf(k3.z, h3.z, a); a = fmaf(k3.w, h3.w, a);
                #pragma unroll
                for (int o = 16; o > 0; o >>= 1) a += __shfl_xor_sync(0xffffffffu, a, o);
                float e = __expf(a * SCALE);
                if (it == 0) e0 = e; else e1 = e;
                den += e;
                acc0 = fmaf(e, g_WV[(size_t)t*Vv + lane], acc0);
                if (lane < Vv - 32)
                    acc1 = fmaf(e, g_WV[(size_t)t*Vv + 32 + lane], acc1);
            }
            sU[wid][lane] = acc0;
            if (lane < Vv - 32) sU[wid][32 + lane] = acc1;
            if (lane == 0) sDen[wid] = den;
        }
        __syncthreads();

        // ---- publish tagged partials ----
        if (tid < Vv) {
            float a = 0.f;
            #pragma unroll
            for (int w = 0; w < 32; ++w) a += sU[w][tid];
            stcg2(&g_pUT[tid*NB + b], make_float2(a, tagf));
        } else if (tid == Vv) {
            float d = 0.f;
            #pragma unroll
            for (int w = 0; w < 32; ++w) d += sDen[w];
            stcg2(&g_pUT[Vv*NB + b], make_float2(d, tagf));
        }

        // ---- gh = w_hh @ h(s), tag s+1: lands during reducer's reduce ----
        GH_PUBLISH(tagf);
    }

    // ---- tail: consume verdict(199) for final attention row ----
    {
        const float ptag = (float)MAXLEN;
        int done = (tid == 0) ? 0 : 1;
        for (;;) {
            if (!done) {
                float4 v = ldcg4(&g_verdR[(b & (NCPY-1))*8]);
                if (v.z >= ptag) { s_vd = v; done = 1; }
            }
            if (__syncthreads_and(done)) break;
        }
        if (lane == 0) {
            float inv = s_vd.y;
            attn[(size_t)(MAXLEN-1)*TENC + t0 + wid     ] = e0 * inv;
            attn[(size_t)(MAXLEN-1)*TENC + t0 + wid + 32] = e1 * inv;
        }
    }
}

// ---------------------------------------------------------------------------
extern "C" void kernel_launch(void* const* d_in, const int* in_sizes, int n_in,
                              void* d_out, int out_size)
{
    const float* enc    = (const float*)d_in[0];
    const float* hidden = (const float*)d_in[1];
    const float* embed  = (const float*)d_in[2];
    const float* w_ih   = (const float*)d_in[3];
    const float* w_hh   = (const float*)d_in[4];
    const float* b_ih   = (const float*)d_in[5];
    const float* b_hh   = (const float*)d_in[6];
    const float* w_out  = (const float*)d_in[7];
    const float* b_out  = (const float*)d_in[8];
    float*       out    = (float*)d_out;

    cudaFuncSetAttribute(gi_kernel, cudaFuncAttributeMaxDynamicSharedMemorySize, 81920);
    cudaFuncSetAttribute(wv_kernel, cudaFuncAttributeMaxDynamicSharedMemorySize, 81920);

    reset_kernel<<<1, 1024>>>();
    gi_kernel<<<192, 256, 81920>>>(w_ih, b_ih, embed);
    wv_kernel<<<256, 256, 81920>>>(enc, w_out);
    dec_main<<<NB + 1, TPB>>>(enc, hidden, w_hh, b_hh, w_out, b_out, out);
}

// round 15
// speedup vs baseline: 1.0306x; 1.0306x over previous
#include <cuda_runtime.h>
#include <math.h>

#define Vv      40
#define Ee      512
#define Hh      512
#define DKk     512
#define DVv     512
#define TENC    8192
#define MAXLEN  200
#define EOSI    38
#define SCALE   0.04419417382415922f   /* 1/sqrt(512) */

#define NB      128          /* worker blocks: 64 keys, 4 gh-rows each */
#define TPB     1024
#define ROWS_PB 4
#define KEYS_PB 64
#define NCPY    16           /* h-line replication */

// -------- persistent device scratch --------
__device__ float  g_GIT[Vv*3*Hh];                    // [best][1536]
__device__ float  g_WV[TENC*Vv];                     // values @ w_out[:, :512]^T
__device__ __align__(16) float4 g_hT4R[NCPY][Hh/2];  // {h2i, h2i+1, invden(s-1), tag}
__device__ __align__(16) float2 g_pUT[(Vv+1)*NB];    // rows 0..39 pU, row 40 denom {val,tag}
__device__ __align__(16) float2 g_ghT[3*Hh];         // {w_hh@h row-gate, tag}, idx row*3+gate

// -------- weak L2-direct vector ops --------
__device__ __forceinline__ float2 ldcg2(const float2* p) {
    float2 v;
    asm volatile("ld.global.cg.v2.f32 {%0,%1},[%2];"
                 : "=f"(v.x), "=f"(v.y) : "l"(p) : "memory");
    return v;
}
__device__ __forceinline__ float4 ldcg4(const float4* p) {
    float4 v;
    asm volatile("ld.global.cg.v4.f32 {%0,%1,%2,%3},[%4];"
                 : "=f"(v.x), "=f"(v.y), "=f"(v.z), "=f"(v.w) : "l"(p) : "memory");
    return v;
}
__device__ __forceinline__ void stcg2(float2* p, float2 v) {
    asm volatile("st.global.cg.v2.f32 [%0],{%1,%2};"
                 :: "l"(p), "f"(v.x), "f"(v.y) : "memory");
}
__device__ __forceinline__ void stcg4(float4* p, float4 v) {
    asm volatile("st.global.cg.v4.f32 [%0],{%1,%2,%3,%4};"
                 :: "l"(p), "f"(v.x), "f"(v.y), "f"(v.z), "f"(v.w) : "memory");
}

// -------- reset tags every launch (graph-replay safe) --------
__global__ void reset_kernel()
{
    int tid = threadIdx.x;
    for (int i = tid; i < (Vv+1)*NB; i += blockDim.x) g_pUT[i] = make_float2(0.f, 0.f);
    for (int i = tid; i < NCPY*Hh/2; i += blockDim.x)
        ((float4*)g_hT4R)[i] = make_float4(0.f,0.f,0.f,0.f);
    for (int i = tid; i < 3*Hh; i += blockDim.x) g_ghT[i] = make_float2(0.f, 0.f);
}

// -------- GIT[v][gid] = dot(w_ih[gid], embed[v]) + b_ih[gid] ----------------
__global__ void gi_kernel(const float* __restrict__ w_ih,
                          const float* __restrict__ b_ih,
                          const float* __restrict__ embed)
{
    extern __shared__ float sE[];
    for (int i = threadIdx.x; i < Vv*Ee; i += blockDim.x) sE[i] = embed[i];
    __syncthreads();

    int lane = threadIdx.x & 31;
    int gid  = blockIdx.x * (blockDim.x >> 5) + (threadIdx.x >> 5);
    if (gid >= 3*Hh) return;

    float4 wreg[4];
    const float4* wr = (const float4*)(w_ih + (size_t)gid * Ee);
    #pragma unroll
    for (int j = 0; j < 4; ++j) wreg[j] = wr[lane + 32*j];
    float bb = b_ih[gid];

    for (int v = 0; v < Vv; ++v) {
        const float4* ev = (const float4*)(sE + v*Ee);
        float a = 0.f;
        #pragma unroll
        for (int j = 0; j < 4; ++j) {
            float4 e = ev[lane + 32*j];
            a = fmaf(wreg[j].x, e.x, a); a = fmaf(wreg[j].y, e.y, a);
            a = fmaf(wreg[j].z, e.z, a); a = fmaf(wreg[j].w, e.w, a);
        }
        #pragma unroll
        for (int o = 16; o > 0; o >>= 1) a += __shfl_down_sync(0xffffffffu, a, o);
        if (lane == 0) g_GIT[(size_t)v*(3*Hh) + gid] = a + bb;
    }
}

// -------- WV[t][k] = dot(values[t], w_out[k][0:512]) ------------------------
__global__ void wv_kernel(const float* __restrict__ enc,
                          const float* __restrict__ w_out)
{
    extern __shared__ float sW[];
    for (int i = threadIdx.x; i < Vv*DVv; i += blockDim.x) {
        int k = i / DVv, j = i % DVv;
        sW[i] = w_out[(size_t)k*(DVv+Hh) + j];
    }
    __syncthreads();

    int lane  = threadIdx.x & 31;
    int gw    = blockIdx.x * (blockDim.x >> 5) + (threadIdx.x >> 5);
    int wspan = gridDim.x  * (blockDim.x >> 5);

    for (int t = gw; t < TENC; t += wspan) {
        float4 vreg[4];
        const float4* vr = (const float4*)(enc + (size_t)t*(DKk+DVv) + DKk);
        #pragma unroll
        for (int j = 0; j < 4; ++j) vreg[j] = vr[lane + 32*j];
        for (int k = 0; k < Vv; ++k) {
            const float4* wk = (const float4*)(sW + k*DVv);
            float a = 0.f;
            #pragma unroll
            for (int j = 0; j < 4; ++j) {
                float4 w = wk[lane + 32*j];
                a = fmaf(vreg[j].x, w.x, a); a = fmaf(vreg[j].y, w.y, a);
                a = fmaf(vreg[j].z, w.z, a); a = fmaf(vreg[j].w, w.w, a);
            }
            #pragma unroll
            for (int o = 16; o > 0; o >>= 1) a += __shfl_down_sync(0xffffffffu, a, o);
            if (lane == 0) g_WV[(size_t)t*Vv + k] = a;
        }
    }
}

// -------- persistent decoder: 128 workers + 1 dedicated reducer -------------
__global__ void __launch_bounds__(TPB, 1)
dec_main(const float* __restrict__ enc,
         const float* __restrict__ hidden,
         const float* __restrict__ w_hh,
         const float* __restrict__ b_hh,
         const float* __restrict__ w_out,
         const float* __restrict__ b_out,
         float*       __restrict__ dout)
{
    __shared__ float  h_sh[Hh];
    __shared__ float  h_stage[Hh];
    __shared__ float  sGH[ROWS_PB][3];
    __shared__ float  sU[32][41];
    __shared__ float  sDen[32];
    __shared__ float  sRR[Vv+1][16];
    __shared__ float  sOH[Vv];
    __shared__ float  sGHall[3*Hh];
    __shared__ float  s_invden;
    __shared__ int    s_bi;
    __shared__ float  s_inv;

    const int tid  = threadIdx.x;
    const int wid  = tid >> 5;
    const int lane = tid & 31;
    const int b    = blockIdx.x;

    float* attn = dout + (MAXLEN*Vv + 1);

    // ========================= DEDICATED REDUCER =========================
    if (b == NB) {
        // one-shot h(0) poll (tag 1)
        {
            int done = (tid < Hh/2) ? 0 : 1;
            for (;;) {
                if (!done) {
                    float4 hv = ldcg4(&g_hT4R[0][tid]);
                    if (hv.w >= 1.f) {
                        h_sh[2*tid] = hv.x; h_sh[2*tid + 1] = hv.y;
                        done = 1;
                    }
                }
                if (__syncthreads_and(done)) break;
            }
        }

        int mylen = MAXLEN;
        for (int s = 0; s < MAXLEN; ++s) {
            const float tagf = (float)(s + 1);
            const bool  last = (s == MAXLEN-1);

            // ---- local pOutH: w_out[:,512:] @ h(s)  (L1-resident weights) ----
            {
                int row = wid;                     // rows 0..31
                #pragma unroll
                for (int pass = 0; pass < 2; ++pass) {
                    if (row < Vv) {
                        const float4* wr  = (const float4*)(w_out + (size_t)row*(DVv+Hh) + DVv);
                        const float4* hv4 = (const float4*)h_sh;
                        float acc = 0.f;
                        #pragma unroll
                        for (int j = 0; j < 4; ++j) {
                            float4 w = wr[lane + 32*j], h = hv4[lane + 32*j];
                            acc = fmaf(w.x, h.x, acc); acc = fmaf(w.y, h.y, acc);
                            acc = fmaf(w.z, h.z, acc); acc = fmaf(w.w, h.w, acc);
                        }
                        #pragma unroll
                        for (int o = 16; o > 0; o >>= 1)
                            acc += __shfl_xor_sync(0xffffffffu, acc, o);
                        if (lane == 0) sOH[row] = acc;
                    }
                    row = wid + 32;                // rows 32..39 on warps 0..7
                }
            }

            // ---- single done-cached gather: gh(s) + partials(s) ----
            {
                const int r = tid >> 4, j = tid & 15;
                int dgh = (!last && tid < 3*Hh/2) ? 0 : 1;
                int dpu = (tid < 656) ? 0 : 1;
                for (;;) {
                    if (!dgh) {
                        float4 e = ldcg4(((const float4*)g_ghT) + tid);
                        if (e.y >= tagf && e.w >= tagf) {
                            sGHall[2*tid] = e.x; sGHall[2*tid + 1] = e.z;
                            dgh = 1;
                        }
                    }
                    if (!dpu) {
                        const float4* base = (const float4*)g_pUT + r*(NB/2);
                        float4 a0 = ldcg4(base + j);
                        float4 a1 = ldcg4(base + j + 16);
                        float4 a2 = ldcg4(base + j + 32);
                        float4 a3 = ldcg4(base + j + 48);
                        if (a0.y >= tagf && a0.w >= tagf && a1.y >= tagf && a1.w >= tagf &&
                            a2.y >= tagf && a2.w >= tagf && a3.y >= tagf && a3.w >= tagf) {
                            sRR[r][j] = (a0.x + a0.z) + (a1.x + a1.z)
                                      + (a2.x + a2.z) + (a3.x + a3.z);
                            dpu = 1;
                        }
                    }
                    if (__syncthreads_and(dgh && dpu)) break;
                }
            }

            // ---- warp 0: denom, logits, argmax ----
            float v1 = 0.f, v2 = -3.4e38f;
            if (wid == 0) {
                float d = 0.f;
                #pragma unroll
                for (int q = 0; q < 16; ++q) d += sRR[Vv][q];
                float inv = 1.0f / d;

                int k1 = lane, k2 = lane + 32;
                {
                    float a = 0.f;
                    #pragma unroll
                    for (int q = 0; q < 16; ++q) a += sRR[k1][q];
                    v1 = a*inv + sOH[k1] + b_out[k1];
                }
                if (lane < Vv - 32) {
                    float a = 0.f;
                    #pragma unroll
                    for (int q = 0; q < 16; ++q) a += sRR[k2][q];
                    v2 = a*inv + sOH[k2] + b_out[k2];
                }
                float bv; int bi;
                if (v2 > v1) { bv = v2; bi = k2; } else { bv = v1; bi = k1; }
                #pragma unroll
                for (int o = 16; o > 0; o >>= 1) {
                    float ov = __shfl_xor_sync(0xffffffffu, bv, o);
                    int   oi = __shfl_xor_sync(0xffffffffu, bi, o);
                    if (ov > bv || (ov == bv && oi < bi)) { bv = ov; bi = oi; }
                }
                if (lane == 0) { s_bi = bi; s_inv = inv; }
            }
            __syncthreads();

            // ---- full 512-row combine -> h_stage (skipped on last step) ----
            if (!last && tid < Hh) {
                int row = tid;
                const float* git = g_GIT + (size_t)s_bi * (3*Hh);
                float ghr = sGHall[3*row    ] + b_hh[row];
                float ghz = sGHall[3*row + 1] + b_hh[Hh + row];
                float ghn = sGHall[3*row + 2] + b_hh[2*Hh + row];
                float gir = git[row], giz = git[Hh + row], gin = git[2*Hh + row];
                float rr = 1.f/(1.f + __expf(-(gir + ghr)));
                float zz = 1.f/(1.f + __expf(-(giz + ghz)));
                float x  = gin + rr*ghn;
                float ex = __expf(2.f*x);
                float nn = (ex - 1.f)/(ex + 1.f);
                h_stage[row] = (1.f - zz)*nn + zz*h_sh[row];
            }
            __syncthreads();

            // ---- publish h(s+1)+invden(s), tag s+2, all copies ----
            if (tid < Hh/2) {
                float ha = last ? 0.f : h_stage[2*tid];
                float hb = last ? 0.f : h_stage[2*tid + 1];
                float4 pk = make_float4(ha, hb, s_inv, tagf + 1.f);
                #pragma unroll
                for (int c = 0; c < NCPY; ++c) stcg4(&g_hT4R[c][tid], pk);
            }

            // ---- off critical path: dout logits, lens, h_sh update ----
            if (wid == 0) {
                dout[s*Vv + lane] = v1;
                if (lane < Vv - 32) dout[s*Vv + lane + 32] = v2;
                if (lane == 0) {
                    if (s_bi == EOSI && mylen == MAXLEN) mylen = s;
                    if (last) dout[MAXLEN*Vv] = (float)mylen;    // lens
                }
            }
            if (!last && tid < Hh) h_sh[tid] = h_stage[tid];
            __syncthreads();   // RACE FIX: order h_sh update before next pOutH read
        }
        return;
    }

    // ========================= WORKER BLOCKS =========================
    const int t0   = b * KEYS_PB;
    const int row0 = b * ROWS_PB;
    float e0 = 0.f, e1 = 0.f;

    #define GH_PUBLISH(TAGF)                                                       \
    do {                                                                           \
        if (wid < 12) {                                                            \
            int rl = wid / 3, gate = wid % 3;                                      \
            const float4* wr = (const float4*)(w_hh +                              \
                               (size_t)(gate*Hh + row0 + rl) * Hh);                \
            const float4* hv4g = (const float4*)h_sh;                              \
            float a = 0.f;                                                         \
            _Pragma("unroll")                                                      \
            for (int j = 0; j < 4; ++j) {                                          \
                float4 w = wr[lane + 32*j], h = hv4g[lane + 32*j];                 \
                a = fmaf(w.x, h.x, a); a = fmaf(w.y, h.y, a);                      \
                a = fmaf(w.z, h.z, a); a = fmaf(w.w, h.w, a);                      \
            }                                                                      \
            _Pragma("unroll")                                                      \
            for (int o = 16; o > 0; o >>= 1) a += __shfl_xor_sync(0xffffffffu, a, o); \
            if (lane == 0)                                                         \
                stcg2(&g_ghT[(row0 + rl)*3 + gate], make_float2(a, (TAGF)));       \
        }                                                                          \
    } while (0)

    // ---- prologue: h(-1)=hidden; gh(hidden) in smem; distributed h(0) ----
    if (tid < Hh/4) ((float4*)h_sh)[tid] = ((const float4*)hidden)[tid];
    __syncthreads();
    if (wid < 12) {
        int rl = wid / 3, gate = wid % 3;
        const float4* wr = (const float4*)(w_hh + (size_t)(gate*Hh + row0 + rl) * Hh);
        const float4* hv4g = (const float4*)h_sh;
        float a = 0.f;
        #pragma unroll
        for (int j = 0; j < 4; ++j) {
            float4 w = wr[lane + 32*j], h = hv4g[lane + 32*j];
            a = fmaf(w.x, h.x, a); a = fmaf(w.y, h.y, a);
            a = fmaf(w.z, h.z, a); a = fmaf(w.w, h.w, a);
        }
        #pragma unroll
        for (int o = 16; o > 0; o >>= 1) a += __shfl_xor_sync(0xffffffffu, a, o);
        if (lane == 0) sGH[rl][gate] = a;
    }
    __syncthreads();
    if (wid == 0) {                              // distributed h(0), tag 1
        float hnv = 0.f;
        if (lane < ROWS_PB) {
            int row = row0 + lane;
            const float* git = g_GIT + (size_t)EOSI * (3*Hh);
            float ghr = sGH[lane][0] + b_hh[row];
            float ghz = sGH[lane][1] + b_hh[Hh + row];
            float ghn = sGH[lane][2] + b_hh[2*Hh + row];
            float gir = git[row], giz = git[Hh + row], gin = git[2*Hh + row];
            float rr = 1.f/(1.f + __expf(-(gir + ghr)));
            float zz = 1.f/(1.f + __expf(-(giz + ghz)));
            float x  = gin + rr*ghn;
            float ex = __expf(2.f*x);
            float nn = (ex - 1.f)/(ex + 1.f);
            hnv = (1.f - zz)*nn + zz*h_sh[row];
        }
        float up = __shfl_down_sync(0xffffffffu, hnv, 1);
        if (lane == 0) {
            float4 pk = make_float4(hnv, up, 0.f, 1.f);
            #pragma unroll
            for (int c = 0; c < NCPY; ++c) stcg4(&g_hT4R[c][2*b], pk);
        }
        if (lane == 2) {
            float4 pk = make_float4(hnv, up, 0.f, 1.f);
            #pragma unroll
            for (int c = 0; c < NCPY; ++c) stcg4(&g_hT4R[c][2*b + 1], pk);
        }
    }

    for (int s = 0; s < MAXLEN; ++s) {
        const float tagf = (float)(s + 1);

        // ---- poll h(s)+invden(s-1), done-cached, single target ----
        {
            int done = (tid < Hh/2) ? 0 : 1;
            for (;;) {
                if (!done) {
                    float4 hv = ldcg4(&g_hT4R[b & (NCPY-1)][tid]);
                    if (hv.w >= tagf) {
                        h_sh[2*tid] = hv.x; h_sh[2*tid + 1] = hv.y;
                        if (tid == 0) s_invden = hv.z;
                        done = 1;
                    }
                }
                if (__syncthreads_and(done)) break;
            }
        }

        // ---- store normalized attention row (s-1) from registers ----
        if (s > 0 && lane == 0) {
            float inv = s_invden;
            attn[(size_t)(s-1)*TENC + t0 + wid     ] = e0 * inv;
            attn[(size_t)(s-1)*TENC + t0 + wid + 32] = e1 * inv;
        }

        // ---- gh = w_hh @ h(s), tag s+1: early, lands in reducer dead time ----
        if (s < MAXLEN-1) GH_PUBLISH(tagf);

        // ---- attention over this block's 64 keys (L1-resident, interleaved) ----
        {
            const float4* hv4 = (const float4*)h_sh;
            float4 h0 = hv4[lane], h1 = hv4[lane+32], h2 = hv4[lane+64], h3 = hv4[lane+96];
            int ta = t0 + wid, tb = t0 + wid + 32;
            const float4* ka = (const float4*)(enc + (size_t)ta*(DKk+DVv));
            const float4* kb = (const float4*)(enc + (size_t)tb*(DKk+DVv));
            float a0 = 0.f, a1 = 0.f;
            {
                float4 p0 = ka[lane], p1 = ka[lane+32], p2 = ka[lane+64], p3 = ka[lane+96];
                a0 = fmaf(p0.x, h0.x, a0); a0 = fmaf(p0.y, h0.y, a0);
                a0 = fmaf(p0.z, h0.z, a0); a0 = fmaf(p0.w, h0.w, a0);
                a0 = fmaf(p1.x, h1.x, a0); a0 = fmaf(p1.y, h1.y, a0);
                a0 = fmaf(p1.z, h1.z, a0); a0 = fmaf(p1.w, h1.w, a0);
                a0 = fmaf(p2.x, h2.x, a0); a0 = fmaf(p2.y, h2.y, a0);
                a0 = fmaf(p2.z, h2.z, a0); a0 = fmaf(p2.w, h2.w, a0);
                a0 = fmaf(p3.x, h3.x, a0); a0 = fmaf(p3.y, h3.y, a0);
                a0 = fmaf(p3.z, h3.z, a0); a0 = fmaf(p3.w, h3.w, a0);
            }
            {
                float4 q0 = kb[lane], q1 = kb[lane+32], q2 = kb[lane+64], q3 = kb[lane+96];
                a1 = fmaf(q0.x, h0.x, a1); a1 = fmaf(q0.y, h0.y, a1);
                a1 = fmaf(q0.z, h0.z, a1); a1 = fmaf(q0.w, h0.w, a1);
                a1 = fmaf(q1.x, h1.x, a1); a1 = fmaf(q1.y, h1.y, a1);
                a1 = fmaf(q1.z, h1.z, a1); a1 = fmaf(q1.w, h1.w, a1);
                a1 = fmaf(q2.x, h2.x, a1); a1 = fmaf(q2.y, h2.y, a1);
                a1 = fmaf(q2.z, h2.z, a1); a1 = fmaf(q2.w, h2.w, a1);
                a1 = fmaf(q3.x, h3.x, a1); a1 = fmaf(q3.y, h3.y, a1);
                a1 = fmaf(q3.z, h3.z, a1); a1 = fmaf(q3.w, h3.w, a1);
            }
            #pragma unroll
            for (int o = 16; o > 0; o >>= 1) {       // interleaved shfl chains
                a0 += __shfl_xor_sync(0xffffffffu, a0, o);
                a1 += __shfl_xor_sync(0xffffffffu, a1, o);
            }
            e0 = __expf(a0 * SCALE);
            e1 = __expf(a1 * SCALE);
            float den = e0 + e1;
            float acc0 = e0 * g_WV[(size_t)ta*Vv + lane]
                       + e1 * g_WV[(size_t)tb*Vv + lane];
            float acc1 = 0.f;
            if (lane < Vv - 32)
                acc1 = e0 * g_WV[(size_t)ta*Vv + 32 + lane]
                     + e1 * g_WV[(size_t)tb*Vv + 32 + lane];
            sU[wid][lane] = acc0;
            if (lane < Vv - 32) sU[wid][32 + lane] = acc1;
            if (lane == 0) sDen[wid] = den;
        }
        __syncthreads();

        // ---- publish tagged partials ----
        if (tid < Vv) {
            float a = 0.f;
            #pragma unroll
            for (int w = 0; w < 32; ++w) a += sU[w][tid];
            stcg2(&g_pUT[tid*NB + b], make_float2(a, tagf));
        } else if (tid == Vv) {
            float d = 0.f;
            #pragma unroll
            for (int w = 0; w < 32; ++w) d += sDen[w];
            stcg2(&g_pUT[Vv*NB + b], make_float2(d, tagf));
        }
    }

    // ---- tail: poll final invden(199) (tag 201) for last attention row ----
    {
        const float ftag = (float)(MAXLEN + 1);
        int done = (tid == 0) ? 0 : 1;
        for (;;) {
            if (!done) {
                float4 hv = ldcg4(&g_hT4R[b & (NCPY-1)][0]);
                if (hv.w >= ftag) { s_invden = hv.z; done = 1; }
            }
            if (__syncthreads_and(done)) break;
        }
        if (lane == 0) {
            float inv = s_invden;
            attn[(size_t)(MAXLEN-1)*TENC + t0 + wid     ] = e0 * inv;
            attn[(size_t)(MAXLEN-1)*TENC + t0 + wid + 32] = e1 * inv;
        }
    }
}

// ---------------------------------------------------------------------------
extern "C" void kernel_launch(void* const* d_in, const int* in_sizes, int n_in,
                              void* d_out, int out_size)
{
    const float* enc    = (const float*)d_in[0];
    const float* hidden = (const float*)d_in[1];
    const float* embed  = (const float*)d_in[2];
    const float* w_ih   = (const float*)d_in[3];
    const float* w_hh   = (const float*)d_in[4];
    const float* b_ih   = (const float*)d_in[5];
    const float* b_hh   = (const float*)d_in[6];
    const float* w_out  = (const float*)d_in[7];
    const float* b_out  = (const float*)d_in[8];
    float*       out    = (float*)d_out;

    cudaFuncSetAttribute(gi_kernel, cudaFuncAttributeMaxDynamicSharedMemorySize, 81920);
    cudaFuncSetAttribute(wv_kernel, cudaFuncAttributeMaxDynamicSharedMemorySize, 81920);

    reset_kernel<<<1, 1024>>>();
    gi_kernel<<<192, 256, 81920>>>(w_ih, b_ih, embed);
    wv_kernel<<<256, 256, 81920>>>(enc, w_out);
    dec_main<<<NB + 1, TPB>>>(enc, hidden, w_hh, b_hh, w_out, b_out, out);
}

// round 16
// speedup vs baseline: 1.0479x; 1.0168x over previous
#include <cuda_runtime.h>
#include <math.h>

#define Vv      40
#define Ee      512
#define Hh      512
#define DKk     512
#define DVv     512
#define TENC    8192
#define MAXLEN  200
#define EOSI    38
#define SCALE   0.04419417382415922f   /* 1/sqrt(512) */

#define NB      128          /* worker blocks: 64 keys, 4 gh-rows each */
#define TPB     1024
#define ROWS_PB 4
#define KEYS_PB 64
#define NCPY    16           /* h-line replication */

// -------- persistent device scratch --------
__device__ float  g_GIT[Vv*3*Hh];                    // [best][1536]
__device__ float  g_WV[TENC*Vv];                     // values @ w_out[:, :512]^T
__device__ __align__(16) float4 g_hT4R[NCPY][Hh/2];  // {h2i, h2i+1, invden(s-1), tag}
__device__ __align__(16) float2 g_pUT[(Vv+1)*NB];    // rows 0..39 pU, row 40 denom {val,tag}
__device__ __align__(16) float2 g_ghT[3*Hh];         // {w_hh@h row-gate, tag}, idx row*3+gate

// -------- weak L2-direct vector ops --------
__device__ __forceinline__ float2 ldcg2(const float2* p) {
    float2 v;
    asm volatile("ld.global.cg.v2.f32 {%0,%1},[%2];"
                 : "=f"(v.x), "=f"(v.y) : "l"(p) : "memory");
    return v;
}
__device__ __forceinline__ float4 ldcg4(const float4* p) {
    float4 v;
    asm volatile("ld.global.cg.v4.f32 {%0,%1,%2,%3},[%4];"
                 : "=f"(v.x), "=f"(v.y), "=f"(v.z), "=f"(v.w) : "l"(p) : "memory");
    return v;
}
__device__ __forceinline__ void stcg2(float2* p, float2 v) {
    asm volatile("st.global.cg.v2.f32 [%0],{%1,%2};"
                 :: "l"(p), "f"(v.x), "f"(v.y) : "memory");
}
__device__ __forceinline__ void stcg4(float4* p, float4 v) {
    asm volatile("st.global.cg.v4.f32 [%0],{%1,%2,%3,%4};"
                 :: "l"(p), "f"(v.x), "f"(v.y), "f"(v.z), "f"(v.w) : "memory");
}

// -------- reset tags every launch (graph-replay safe) --------
__global__ void reset_kernel()
{
    int tid = threadIdx.x;
    for (int i = tid; i < (Vv+1)*NB; i += blockDim.x) g_pUT[i] = make_float2(0.f, 0.f);
    for (int i = tid; i < NCPY*Hh/2; i += blockDim.x)
        ((float4*)g_hT4R)[i] = make_float4(0.f,0.f,0.f,0.f);
    for (int i = tid; i < 3*Hh; i += blockDim.x) g_ghT[i] = make_float2(0.f, 0.f);
}

// -------- GIT[v][gid] = dot(w_ih[gid], embed[v]) + b_ih[gid] ----------------
__global__ void gi_kernel(const float* __restrict__ w_ih,
                          const float* __restrict__ b_ih,
                          const float* __restrict__ embed)
{
    extern __shared__ float sE[];
    for (int i = threadIdx.x; i < Vv*Ee; i += blockDim.x) sE[i] = embed[i];
    __syncthreads();

    int lane = threadIdx.x & 31;
    int gid  = blockIdx.x * (blockDim.x >> 5) + (threadIdx.x >> 5);
    if (gid >= 3*Hh) return;

    float4 wreg[4];
    const float4* wr = (const float4*)(w_ih + (size_t)gid * Ee);
    #pragma unroll
    for (int j = 0; j < 4; ++j) wreg[j] = wr[lane + 32*j];
    float bb = b_ih[gid];

    for (int v = 0; v < Vv; ++v) {
        const float4* ev = (const float4*)(sE + v*Ee);
        float a = 0.f;
        #pragma unroll
        for (int j = 0; j < 4; ++j) {
            float4 e = ev[lane + 32*j];
            a = fmaf(wreg[j].x, e.x, a); a = fmaf(wreg[j].y, e.y, a);
            a = fmaf(wreg[j].z, e.z, a); a = fmaf(wreg[j].w, e.w, a);
        }
        #pragma unroll
        for (int o = 16; o > 0; o >>= 1) a += __shfl_down_sync(0xffffffffu, a, o);
        if (lane == 0) g_GIT[(size_t)v*(3*Hh) + gid] = a + bb;
    }
}

// -------- WV[t][k] = dot(values[t], w_out[k][0:512]) ------------------------
__global__ void wv_kernel(const float* __restrict__ enc,
                          const float* __restrict__ w_out)
{
    extern __shared__ float sW[];
    for (int i = threadIdx.x; i < Vv*DVv; i += blockDim.x) {
        int k = i / DVv, j = i % DVv;
        sW[i] = w_out[(size_t)k*(DVv+Hh) + j];
    }
    __syncthreads();

    int lane  = threadIdx.x & 31;
    int gw    = blockIdx.x * (blockDim.x >> 5) + (threadIdx.x >> 5);
    int wspan = gridDim.x  * (blockDim.x >> 5);

    for (int t = gw; t < TENC; t += wspan) {
        float4 vreg[4];
        const float4* vr = (const float4*)(enc + (size_t)t*(DKk+DVv) + DKk);
        #pragma unroll
        for (int j = 0; j < 4; ++j) vreg[j] = vr[lane + 32*j];
        for (int k = 0; k < Vv; ++k) {
            const float4* wk = (const float4*)(sW + k*DVv);
            float a = 0.f;
            #pragma unroll
            for (int j = 0; j < 4; ++j) {
                float4 w = wk[lane + 32*j];
                a = fmaf(vreg[j].x, w.x, a); a = fmaf(vreg[j].y, w.y, a);
                a = fmaf(vreg[j].z, w.z, a); a = fmaf(vreg[j].w, w.w, a);
            }
            #pragma unroll
            for (int o = 16; o > 0; o >>= 1) a += __shfl_down_sync(0xffffffffu, a, o);
            if (lane == 0) g_WV[(size_t)t*Vv + k] = a;
        }
    }
}

// -------- persistent decoder: 128 workers + 1 dedicated reducer -------------
__global__ void __launch_bounds__(TPB, 1)
dec_main(const float* __restrict__ enc,
         const float* __restrict__ hidden,
         const float* __restrict__ w_hh,
         const float* __restrict__ b_hh,
         const float* __restrict__ w_out,
         const float* __restrict__ b_out,
         float*       __restrict__ dout)
{
    __shared__ float  h_sh[Hh];
    __shared__ float  h_stage[Hh];
    __shared__ float  sGH[ROWS_PB][3];
    __shared__ float  sU[32][41];
    __shared__ float  sDen[32];
    __shared__ float  sRR[Vv+1][16];
    __shared__ float  sOH[Vv];
    __shared__ float  sGHall[3*Hh];
    __shared__ float  s_invden;
    __shared__ int    s_bi;
    __shared__ float  s_inv;

    const int tid  = threadIdx.x;
    const int wid  = tid >> 5;
    const int lane = tid & 31;
    const int b    = blockIdx.x;

    float* attn = dout + (MAXLEN*Vv + 1);

    // ========================= DEDICATED REDUCER =========================
    if (b == NB) {
        // one-shot h(0) poll (tag 1)
        {
            int done = (tid < Hh/2) ? 0 : 1;
            for (;;) {
                if (!done) {
                    float4 hv = ldcg4(&g_hT4R[0][tid]);
                    if (hv.w >= 1.f) {
                        h_sh[2*tid] = hv.x; h_sh[2*tid + 1] = hv.y;
                        done = 1;
                    }
                }
                if (__syncthreads_and(done)) break;
            }
        }

        int mylen = MAXLEN;
        for (int s = 0; s < MAXLEN; ++s) {
            const float tagf = (float)(s + 1);
            const bool  last = (s == MAXLEN-1);

            // ---- local pOutH: w_out[:,512:] @ h(s)  (overlaps worker attn) ----
            {
                int row = wid;                     // rows 0..31, then 32..39
                #pragma unroll
                for (int pass = 0; pass < 2; ++pass) {
                    if (row < Vv) {
                        const float4* wr  = (const float4*)(w_out + (size_t)row*(DVv+Hh) + DVv);
                        const float4* hv4 = (const float4*)h_sh;
                        float acc = 0.f;
                        #pragma unroll
                        for (int j = 0; j < 4; ++j) {
                            float4 w = wr[lane + 32*j], h = hv4[lane + 32*j];
                            acc = fmaf(w.x, h.x, acc); acc = fmaf(w.y, h.y, acc);
                            acc = fmaf(w.z, h.z, acc); acc = fmaf(w.w, h.w, acc);
                        }
                        #pragma unroll
                        for (int o = 16; o > 0; o >>= 1)
                            acc += __shfl_xor_sync(0xffffffffu, acc, o);
                        if (lane == 0) sOH[row] = acc;
                    }
                    row = wid + 32;
                }
            }

            // ---- loop1: partials, done-cached ----
            {
                const int r = tid >> 4, j = tid & 15;
                int done = (tid < 656) ? 0 : 1;
                for (;;) {
                    if (!done) {
                        const float4* base = (const float4*)g_pUT + r*(NB/2);
                        float4 a0 = ldcg4(base + j);
                        float4 a1 = ldcg4(base + j + 16);
                        float4 a2 = ldcg4(base + j + 32);
                        float4 a3 = ldcg4(base + j + 48);
                        if (a0.y >= tagf && a0.w >= tagf && a1.y >= tagf && a1.w >= tagf &&
                            a2.y >= tagf && a2.w >= tagf && a3.y >= tagf && a3.w >= tagf) {
                            sRR[r][j] = (a0.x + a0.z) + (a1.x + a1.z)
                                      + (a2.x + a2.z) + (a3.x + a3.z);
                            done = 1;
                        }
                    }
                    if (__syncthreads_and(done)) break;
                }
            }

            // ---- warp 0: denom, logits, argmax  (overlaps loop2 polling) ----
            float v1 = 0.f, v2 = -3.4e38f;
            if (wid == 0) {
                float d = 0.f;
                #pragma unroll
                for (int q = 0; q < 16; ++q) d += sRR[Vv][q];
                float inv = 1.0f / d;

                int k1 = lane, k2 = lane + 32;
                {
                    float a = 0.f;
                    #pragma unroll
                    for (int q = 0; q < 16; ++q) a += sRR[k1][q];
                    v1 = a*inv + sOH[k1] + b_out[k1];
                }
                if (lane < Vv - 32) {
                    float a = 0.f;
                    #pragma unroll
                    for (int q = 0; q < 16; ++q) a += sRR[k2][q];
                    v2 = a*inv + sOH[k2] + b_out[k2];
                }
                float bv; int bi;
                if (v2 > v1) { bv = v2; bi = k2; } else { bv = v1; bi = k1; }
                #pragma unroll
                for (int o = 16; o > 0; o >>= 1) {
                    float ov = __shfl_xor_sync(0xffffffffu, bv, o);
                    int   oi = __shfl_xor_sync(0xffffffffu, bi, o);
                    if (ov > bv || (ov == bv && oi < bi)) { bv = ov; bi = oi; }
                }
                if (lane == 0) { s_bi = bi; s_inv = inv; }
            }

            // ---- loop2: gh, done-cached (arrives during argmax) ----
            if (!last) {
                int done = (tid < 3*Hh/2) ? 0 : 1;
                for (;;) {
                    if (!done) {
                        float4 e = ldcg4(((const float4*)g_ghT) + tid);
                        if (e.y >= tagf && e.w >= tagf) {
                            sGHall[2*tid] = e.x; sGHall[2*tid + 1] = e.z;
                            done = 1;
                        }
                    }
                    if (__syncthreads_and(done)) break;
                }
            } else {
                __syncthreads();                  // order s_bi/s_inv for publish
            }

            // ---- full 512-row combine -> h_stage (skipped on last step) ----
            if (!last && tid < Hh) {
                int row = tid;
                const float* git = g_GIT + (size_t)s_bi * (3*Hh);
                float ghr = sGHall[3*row    ] + b_hh[row];
                float ghz = sGHall[3*row + 1] + b_hh[Hh + row];
                float ghn = sGHall[3*row + 2] + b_hh[2*Hh + row];
                float gir = git[row], giz = git[Hh + row], gin = git[2*Hh + row];
                float rr = 1.f/(1.f + __expf(-(gir + ghr)));
                float zz = 1.f/(1.f + __expf(-(giz + ghz)));
                float x  = gin + rr*ghn;
                float ex = __expf(2.f*x);
                float nn = (ex - 1.f)/(ex + 1.f);
                h_stage[row] = (1.f - zz)*nn + zz*h_sh[row];
            }
            __syncthreads();

            // ---- publish h(s+1)+invden(s), tag s+2: 512 threads, 8 copies each ----
            if (tid < Hh) {
                int line = tid & (Hh/2 - 1);
                int c0   = (tid >> 8) * (NCPY/2);
                float ha = last ? 0.f : h_stage[2*line];
                float hb = last ? 0.f : h_stage[2*line + 1];
                float4 pk = make_float4(ha, hb, s_inv, tagf + 1.f);
                #pragma unroll
                for (int c = 0; c < NCPY/2; ++c) stcg4(&g_hT4R[c0 + c][line], pk);
            }

            // ---- off critical path: dout logits, lens, h_sh update ----
            if (wid == 0) {
                dout[s*Vv + lane] = v1;
                if (lane < Vv - 32) dout[s*Vv + lane + 32] = v2;
                if (lane == 0) {
                    if (s_bi == EOSI && mylen == MAXLEN) mylen = s;
                    if (last) dout[MAXLEN*Vv] = (float)mylen;    // lens
                }
            }
            if (!last && tid < Hh) h_sh[tid] = h_stage[tid];
            __syncthreads();   // order h_sh update before next pOutH read
        }
        return;
    }

    // ========================= WORKER BLOCKS =========================
    const int t0   = b * KEYS_PB;
    const int row0 = b * ROWS_PB;
    float e0 = 0.f, e1 = 0.f;

    #define GH_PUBLISH(TAGF)                                                       \
    do {                                                                           \
        if (wid < 12) {                                                            \
            int rl = wid / 3, gate = wid % 3;                                      \
            const float4* wr = (const float4*)(w_hh +                              \
                               (size_t)(gate*Hh + row0 + rl) * Hh);                \
            const float4* hv4g = (const float4*)h_sh;                              \
            float a = 0.f;                                                         \
            _Pragma("unroll")                                                      \
            for (int j = 0; j < 4; ++j) {                                          \
                float4 w = wr[lane + 32*j], h = hv4g[lane + 32*j];                 \
                a = fmaf(w.x, h.x, a); a = fmaf(w.y, h.y, a);                      \
                a = fmaf(w.z, h.z, a); a = fmaf(w.w, h.w, a);                      \
            }                                                                      \
            _Pragma("unroll")                                                      \
            for (int o = 16; o > 0; o >>= 1) a += __shfl_xor_sync(0xffffffffu, a, o); \
            if (lane == 0)                                                         \
                stcg2(&g_ghT[(row0 + rl)*3 + gate], make_float2(a, (TAGF)));       \
        }                                                                          \
    } while (0)

    // ---- prologue: h(-1)=hidden; gh(hidden) in smem; distributed h(0) ----
    if (tid < Hh/4) ((float4*)h_sh)[tid] = ((const float4*)hidden)[tid];
    __syncthreads();
    if (wid < 12) {
        int rl = wid / 3, gate = wid % 3;
        const float4* wr = (const float4*)(w_hh + (size_t)(gate*Hh + row0 + rl) * Hh);
        const float4* hv4g = (const float4*)h_sh;
        float a = 0.f;
        #pragma unroll
        for (int j = 0; j < 4; ++j) {
            float4 w = wr[lane + 32*j], h = hv4g[lane + 32*j];
            a = fmaf(w.x, h.x, a); a = fmaf(w.y, h.y, a);
            a = fmaf(w.z, h.z, a); a = fmaf(w.w, h.w, a);
        }
        #pragma unroll
        for (int o = 16; o > 0; o >>= 1) a += __shfl_xor_sync(0xffffffffu, a, o);
        if (lane == 0) sGH[rl][gate] = a;
    }
    __syncthreads();
    if (wid == 0) {                              // distributed h(0), tag 1
        float hnv = 0.f;
        if (lane < ROWS_PB) {
            int row = row0 + lane;
            const float* git = g_GIT + (size_t)EOSI * (3*Hh);
            float ghr = sGH[lane][0] + b_hh[row];
            float ghz = sGH[lane][1] + b_hh[Hh + row];
            float ghn = sGH[lane][2] + b_hh[2*Hh + row];
            float gir = git[row], giz = git[Hh + row], gin = git[2*Hh + row];
            float rr = 1.f/(1.f + __expf(-(gir + ghr)));
            float zz = 1.f/(1.f + __expf(-(giz + ghz)));
            float x  = gin + rr*ghn;
            float ex = __expf(2.f*x);
            float nn = (ex - 1.f)/(ex + 1.f);
            hnv = (1.f - zz)*nn + zz*h_sh[row];
        }
        float up = __shfl_down_sync(0xffffffffu, hnv, 1);
        if (lane == 0) {
            float4 pk = make_float4(hnv, up, 0.f, 1.f);
            #pragma unroll
            for (int c = 0; c < NCPY; ++c) stcg4(&g_hT4R[c][2*b], pk);
        }
        if (lane == 2) {
            float4 pk = make_float4(hnv, up, 0.f, 1.f);
            #pragma unroll
            for (int c = 0; c < NCPY; ++c) stcg4(&g_hT4R[c][2*b + 1], pk);
        }
    }

    for (int s = 0; s < MAXLEN; ++s) {
        const float tagf = (float)(s + 1);

        // ---- poll h(s)+invden(s-1), done-cached, single target ----
        {
            int done = (tid < Hh/2) ? 0 : 1;
            for (;;) {
                if (!done) {
                    float4 hv = ldcg4(&g_hT4R[b & (NCPY-1)][tid]);
                    if (hv.w >= tagf) {
                        h_sh[2*tid] = hv.x; h_sh[2*tid + 1] = hv.y;
                        if (tid == 0) s_invden = hv.z;
                        done = 1;
                    }
                }
                if (__syncthreads_and(done)) break;
            }
        }

        // ---- store normalized attention row (s-1) from registers ----
        if (s > 0 && lane == 0) {
            float inv = s_invden;
            attn[(size_t)(s-1)*TENC + t0 + wid     ] = e0 * inv;
            attn[(size_t)(s-1)*TENC + t0 + wid + 32] = e1 * inv;
        }

        // ---- attention over this block's 64 keys — FIRST (critical path) ----
        {
            const float4* hv4 = (const float4*)h_sh;
            float4 h0 = hv4[lane], h1 = hv4[lane+32], h2 = hv4[lane+64], h3 = hv4[lane+96];
            int ta = t0 + wid, tb = t0 + wid + 32;
            const float4* ka = (const float4*)(enc + (size_t)ta*(DKk+DVv));
            const float4* kb = (const float4*)(enc + (size_t)tb*(DKk+DVv));
            float a0 = 0.f, a1 = 0.f;
            {
                float4 p0 = ka[lane], p1 = ka[lane+32], p2 = ka[lane+64], p3 = ka[lane+96];
                a0 = fmaf(p0.x, h0.x, a0); a0 = fmaf(p0.y, h0.y, a0);
                a0 = fmaf(p0.z, h0.z, a0); a0 = fmaf(p0.w, h0.w, a0);
                a0 = fmaf(p1.x, h1.x, a0); a0 = fmaf(p1.y, h1.y, a0);
                a0 = fmaf(p1.z, h1.z, a0); a0 = fmaf(p1.w, h1.w, a0);
                a0 = fmaf(p2.x, h2.x, a0); a0 = fmaf(p2.y, h2.y, a0);
                a0 = fmaf(p2.z, h2.z, a0); a0 = fmaf(p2.w, h2.w, a0);
                a0 = fmaf(p3.x, h3.x, a0); a0 = fmaf(p3.y, h3.y, a0);
                a0 = fmaf(p3.z, h3.z, a0); a0 = fmaf(p3.w, h3.w, a0);
            }
            {
                float4 q0 = kb[lane], q1 = kb[lane+32], q2 = kb[lane+64], q3 = kb[lane+96];
                a1 = fmaf(q0.x, h0.x, a1); a1 = fmaf(q0.y, h0.y, a1);
                a1 = fmaf(q0.z, h0.z, a1); a1 = fmaf(q0.w, h0.w, a1);
                a1 = fmaf(q1.x, h1.x, a1); a1 = fmaf(q1.y, h1.y, a1);
                a1 = fmaf(q1.z, h1.z, a1); a1 = fmaf(q1.w, h1.w, a1);
                a1 = fmaf(q2.x, h2.x, a1); a1 = fmaf(q2.y, h2.y, a1);
                a1 = fmaf(q2.z, h2.z, a1); a1 = fmaf(q2.w, h2.w, a1);
                a1 = fmaf(q3.x, h3.x, a1); a1 = fmaf(q3.y, h3.y, a1);
                a1 = fmaf(q3.z, h3.z, a1); a1 = fmaf(q3.w, h3.w, a1);
            }
            #pragma unroll
            for (int o = 16; o > 0; o >>= 1) {
                a0 += __shfl_xor_sync(0xffffffffu, a0, o);
                a1 += __shfl_xor_sync(0xffffffffu, a1, o);
            }
            e0 = __expf(a0 * SCALE);
            e1 = __expf(a1 * SCALE);
            float den = e0 + e1;
            float acc0 = e0 * g_WV[(size_t)ta*Vv + lane]
                       + e1 * g_WV[(size_t)tb*Vv + lane];
            float acc1 = 0.f;
            if (lane < Vv - 32)
                acc1 = e0 * g_WV[(size_t)ta*Vv + 32 + lane]
                     + e1 * g_WV[(size_t)tb*Vv + 32 + lane];
            sU[wid][lane] = acc0;
            if (lane < Vv - 32) sU[wid][32 + lane] = acc1;
            if (lane == 0) sDen[wid] = den;
        }
        __syncthreads();

        // ---- publish tagged partials ----
        if (tid < Vv) {
            float a = 0.f;
            #pragma unroll
            for (int w = 0; w < 32; ++w) a += sU[w][tid];
            stcg2(&g_pUT[tid*NB + b], make_float2(a, tagf));
        } else if (tid == Vv) {
            float d = 0.f;
            #pragma unroll
            for (int w = 0; w < 32; ++w) d += sDen[w];
            stcg2(&g_pUT[Vv*NB + b], make_float2(d, tagf));
        }

        // ---- gh = w_hh @ h(s): AFTER partials; lands during reducer argmax ----
        if (s < MAXLEN-1) GH_PUBLISH(tagf);
    }

    // ---- tail: poll final invden(199) (tag 201) for last attention row ----
    {
        const float ftag = (float)(MAXLEN + 1);
        int done = (tid == 0) ? 0 : 1;
        for (;;) {
            if (!done) {
                float4 hv = ldcg4(&g_hT4R[b & (NCPY-1)][0]);
                if (hv.w >= ftag) { s_invden = hv.z; done = 1; }
            }
            if (__syncthreads_and(done)) break;
        }
        if (lane == 0) {
            float inv = s_invden;
            attn[(size_t)(MAXLEN-1)*TENC + t0 + wid     ] = e0 * inv;
            attn[(size_t)(MAXLEN-1)*TENC + t0 + wid + 32] = e1 * inv;
        }
    }
}

// ---------------------------------------------------------------------------
extern "C" void kernel_launch(void* const* d_in, const int* in_sizes, int n_in,
                              void* d_out, int out_size)
{
    const float* enc    = (const float*)d_in[0];
    const float* hidden = (const float*)d_in[1];
    const float* embed  = (const float*)d_in[2];
    const float* w_ih   = (const float*)d_in[3];
    const float* w_hh   = (const float*)d_in[4];
    const float* b_ih   = (const float*)d_in[5];
    const float* b_hh   = (const float*)d_in[6];
    const float* w_out  = (const float*)d_in[7];
    const float* b_out  = (const float*)d_in[8];
    float*       out    = (float*)d_out;

    cudaFuncSetAttribute(gi_kernel, cudaFuncAttributeMaxDynamicSharedMemorySize, 81920);
    cudaFuncSetAttribute(wv_kernel, cudaFuncAttributeMaxDynamicSharedMemorySize, 81920);

    reset_kernel<<<1, 1024>>>();
    gi_kernel<<<192, 256, 81920>>>(w_ih, b_ih, embed);
    wv_kernel<<<256, 256, 81920>>>(enc, w_out);
    dec_main<<<NB + 1, TPB>>>(enc, hidden, w_hh, b_hh, w_out, b_out, out);
}

// round 17
// speedup vs baseline: 1.2384x; 1.1819x over previous
#include <cuda_runtime.h>
#include <math.h>

#define Vv      40
#define Ee      512
#define Hh      512
#define DKk     512
#define DVv     512
#define TENC    8192
#define MAXLEN  200
#define EOSI    38
#define SCALE   0.04419417382415922f   /* 1/sqrt(512) */

#define NB      128          /* worker blocks: 64 keys, 4 gh-rows each */
#define TPB     1024
#define ROWS_PB 4
#define KEYS_PB 64
#define NCPY    8            /* h-line replication (proven-safe level) */

// -------- persistent device scratch --------
__device__ float  g_GIT[Vv*3*Hh];                    // [best][1536]
__device__ float  g_WV[TENC*Vv];                     // values @ w_out[:, :512]^T
__device__ __align__(16) float4 g_hT4R[NCPY][Hh/2];  // {h2i, h2i+1, invden(s-1), tag}
__device__ __align__(16) float2 g_pUT[(Vv+1)*NB];    // rows 0..39 pU, row 40 denom {val,tag}
__device__ __align__(16) float2 g_ghT[3*Hh];         // {w_hh@h row-gate, tag}, idx row*3+gate

// -------- weak L2-direct vector ops --------
__device__ __forceinline__ float2 ldcg2(const float2* p) {
    float2 v;
    asm volatile("ld.global.cg.v2.f32 {%0,%1},[%2];"
                 : "=f"(v.x), "=f"(v.y) : "l"(p) : "memory");
    return v;
}
__device__ __forceinline__ float4 ldcg4(const float4* p) {
    float4 v;
    asm volatile("ld.global.cg.v4.f32 {%0,%1,%2,%3},[%4];"
                 : "=f"(v.x), "=f"(v.y), "=f"(v.z), "=f"(v.w) : "l"(p) : "memory");
    return v;
}
__device__ __forceinline__ void stcg2(float2* p, float2 v) {
    asm volatile("st.global.cg.v2.f32 [%0],{%1,%2};"
                 :: "l"(p), "f"(v.x), "f"(v.y) : "memory");
}
__device__ __forceinline__ void stcg4(float4* p, float4 v) {
    asm volatile("st.global.cg.v4.f32 [%0],{%1,%2,%3,%4};"
                 :: "l"(p), "f"(v.x), "f"(v.y), "f"(v.z), "f"(v.w) : "memory");
}

// -------- reset tags every launch (graph-replay safe) --------
__global__ void reset_kernel()
{
    int tid = threadIdx.x;
    for (int i = tid; i < (Vv+1)*NB; i += blockDim.x) g_pUT[i] = make_float2(0.f, 0.f);
    for (int i = tid; i < NCPY*Hh/2; i += blockDim.x)
        ((float4*)g_hT4R)[i] = make_float4(0.f,0.f,0.f,0.f);
    for (int i = tid; i < 3*Hh; i += blockDim.x) g_ghT[i] = make_float2(0.f, 0.f);
}

// -------- GIT[v][gid] = dot(w_ih[gid], embed[v]) + b_ih[gid] ----------------
__global__ void gi_kernel(const float* __restrict__ w_ih,
                          const float* __restrict__ b_ih,
                          const float* __restrict__ embed)
{
    extern __shared__ float sE[];
    for (int i = threadIdx.x; i < Vv*Ee; i += blockDim.x) sE[i] = embed[i];
    __syncthreads();

    int lane = threadIdx.x & 31;
    int gid  = blockIdx.x * (blockDim.x >> 5) + (threadIdx.x >> 5);
    if (gid >= 3*Hh) return;

    float4 wreg[4];
    const float4* wr = (const float4*)(w_ih + (size_t)gid * Ee);
    #pragma unroll
    for (int j = 0; j < 4; ++j) wreg[j] = wr[lane + 32*j];
    float bb = b_ih[gid];

    for (int v = 0; v < Vv; ++v) {
        const float4* ev = (const float4*)(sE + v*Ee);
        float a = 0.f;
        #pragma unroll
        for (int j = 0; j < 4; ++j) {
            float4 e = ev[lane + 32*j];
            a = fmaf(wreg[j].x, e.x, a); a = fmaf(wreg[j].y, e.y, a);
            a = fmaf(wreg[j].z, e.z, a); a = fmaf(wreg[j].w, e.w, a);
        }
        #pragma unroll
        for (int o = 16; o > 0; o >>= 1) a += __shfl_down_sync(0xffffffffu, a, o);
        if (lane == 0) g_GIT[(size_t)v*(3*Hh) + gid] = a + bb;
    }
}

// -------- WV[t][k] = dot(values[t], w_out[k][0:512]) ------------------------
__global__ void wv_kernel(const float* __restrict__ enc,
                          const float* __restrict__ w_out)
{
    extern __shared__ float sW[];
    for (int i = threadIdx.x; i < Vv*DVv; i += blockDim.x) {
        int k = i / DVv, j = i % DVv;
        sW[i] = w_out[(size_t)k*(DVv+Hh) + j];
    }
    __syncthreads();

    int lane  = threadIdx.x & 31;
    int gw    = blockIdx.x * (blockDim.x >> 5) + (threadIdx.x >> 5);
    int wspan = gridDim.x  * (blockDim.x >> 5);

    for (int t = gw; t < TENC; t += wspan) {
        float4 vreg[4];
        const float4* vr = (const float4*)(enc + (size_t)t*(DKk+DVv) + DKk);
        #pragma unroll
        for (int j = 0; j < 4; ++j) vreg[j] = vr[lane + 32*j];
        for (int k = 0; k < Vv; ++k) {
            const float4* wk = (const float4*)(sW + k*DVv);
            float a = 0.f;
            #pragma unroll
            for (int j = 0; j < 4; ++j) {
                float4 w = wk[lane + 32*j];
                a = fmaf(vreg[j].x, w.x, a); a = fmaf(vreg[j].y, w.y, a);
                a = fmaf(vreg[j].z, w.z, a); a = fmaf(vreg[j].w, w.w, a);
            }
            #pragma unroll
            for (int o = 16; o > 0; o >>= 1) a += __shfl_down_sync(0xffffffffu, a, o);
            if (lane == 0) g_WV[(size_t)t*Vv + k] = a;
        }
    }
}

// -------- persistent decoder: 128 workers + 1 dedicated reducer -------------
__global__ void __launch_bounds__(TPB, 1)
dec_main(const float* __restrict__ enc,
         const float* __restrict__ hidden,
         const float* __restrict__ w_hh,
         const float* __restrict__ b_hh,
         const float* __restrict__ w_out,
         const float* __restrict__ b_out,
         float*       __restrict__ dout)
{
    __shared__ float  h_sh[Hh];
    __shared__ float  h_stage[Hh];
    __shared__ float  sGH[ROWS_PB][3];
    __shared__ float  sU[32][41];
    __shared__ float  sDen[32];
    __shared__ float  sRR[Vv+1][16];
    __shared__ float  sOH[Vv];
    __shared__ float  sGHall[3*Hh];
    __shared__ float  s_invden;
    __shared__ int    s_bi;
    __shared__ float  s_inv;

    const int tid  = threadIdx.x;
    const int wid  = tid >> 5;
    const int lane = tid & 31;
    const int b    = blockIdx.x;

    float* attn = dout + (MAXLEN*Vv + 1);

    // ========================= DEDICATED REDUCER =========================
    if (b == NB) {
        // one-shot h(0) poll (tag 1)
        {
            int done = (tid < Hh/2) ? 0 : 1;
            for (;;) {
                if (!done) {
                    float4 hv = ldcg4(&g_hT4R[0][tid]);
                    if (hv.w >= 1.f) {
                        h_sh[2*tid] = hv.x; h_sh[2*tid + 1] = hv.y;
                        done = 1;
                    }
                }
                if (__syncthreads_and(done)) break;
            }
        }

        int mylen = MAXLEN;
        for (int s = 0; s < MAXLEN; ++s) {
            const float tagf = (float)(s + 1);
            const bool  last = (s == MAXLEN-1);

            // ---- local pOutH: w_out[:,512:] @ h(s)  (overlaps worker attn) ----
            {
                int row = wid;                     // rows 0..31, then 32..39
                #pragma unroll
                for (int pass = 0; pass < 2; ++pass) {
                    if (row < Vv) {
                        const float4* wr  = (const float4*)(w_out + (size_t)row*(DVv+Hh) + DVv);
                        const float4* hv4 = (const float4*)h_sh;
                        float acc = 0.f;
                        #pragma unroll
                        for (int j = 0; j < 4; ++j) {
                            float4 w = wr[lane + 32*j], h = hv4[lane + 32*j];
                            acc = fmaf(w.x, h.x, acc); acc = fmaf(w.y, h.y, acc);
                            acc = fmaf(w.z, h.z, acc); acc = fmaf(w.w, h.w, acc);
                        }
                        #pragma unroll
                        for (int o = 16; o > 0; o >>= 1)
                            acc += __shfl_xor_sync(0xffffffffu, acc, o);
                        if (lane == 0) sOH[row] = acc;
                    }
                    row = wid + 32;
                }
            }

            // ---- loop1: partials, done-cached ----
            {
                const int r = tid >> 4, j = tid & 15;
                int done = (tid < 656) ? 0 : 1;
                for (;;) {
                    if (!done) {
                        const float4* base = (const float4*)g_pUT + r*(NB/2);
                        float4 a0 = ldcg4(base + j);
                        float4 a1 = ldcg4(base + j + 16);
                        float4 a2 = ldcg4(base + j + 32);
                        float4 a3 = ldcg4(base + j + 48);
                        if (a0.y >= tagf && a0.w >= tagf && a1.y >= tagf && a1.w >= tagf &&
                            a2.y >= tagf && a2.w >= tagf && a3.y >= tagf && a3.w >= tagf) {
                            sRR[r][j] = (a0.x + a0.z) + (a1.x + a1.z)
                                      + (a2.x + a2.z) + (a3.x + a3.z);
                            done = 1;
                        }
                    }
                    if (__syncthreads_and(done)) break;
                }
            }

            // ---- warp 0: denom, logits, argmax  (overlaps loop2 polling) ----
            float v1 = 0.f, v2 = -3.4e38f;
            if (wid == 0) {
                float d = 0.f;
                #pragma unroll
                for (int q = 0; q < 16; ++q) d += sRR[Vv][q];
                float inv = 1.0f / d;

                int k1 = lane, k2 = lane + 32;
                {
                    float a = 0.f;
                    #pragma unroll
                    for (int q = 0; q < 16; ++q) a += sRR[k1][q];
                    v1 = a*inv + sOH[k1] + b_out[k1];
                }
                if (lane < Vv - 32) {
                    float a = 0.f;
                    #pragma unroll
                    for (int q = 0; q < 16; ++q) a += sRR[k2][q];
                    v2 = a*inv + sOH[k2] + b_out[k2];
                }
                float bv; int bi;
                if (v2 > v1) { bv = v2; bi = k2; } else { bv = v1; bi = k1; }
                #pragma unroll
                for (int o = 16; o > 0; o >>= 1) {
                    float ov = __shfl_xor_sync(0xffffffffu, bv, o);
                    int   oi = __shfl_xor_sync(0xffffffffu, bi, o);
                    if (ov > bv || (ov == bv && oi < bi)) { bv = ov; bi = oi; }
                }
                if (lane == 0) { s_bi = bi; s_inv = inv; }
            }

            // ---- loop2: gh, done-cached (arrives during argmax) ----
            if (!last) {
                int done = (tid < 3*Hh/2) ? 0 : 1;
                for (;;) {
                    if (!done) {
                        float4 e = ldcg4(((const float4*)g_ghT) + tid);
                        if (e.y >= tagf && e.w >= tagf) {
                            sGHall[2*tid] = e.x; sGHall[2*tid + 1] = e.z;
                            done = 1;
                        }
                    }
                    if (__syncthreads_and(done)) break;
                }
            } else {
                __syncthreads();                  // order s_bi/s_inv for publish
            }

            // ---- full 512-row combine -> h_stage (skipped on last step) ----
            if (!last && tid < Hh) {
                int row = tid;
                const float* git = g_GIT + (size_t)s_bi * (3*Hh);
                float ghr = sGHall[3*row    ] + b_hh[row];
                float ghz = sGHall[3*row + 1] + b_hh[Hh + row];
                float ghn = sGHall[3*row + 2] + b_hh[2*Hh + row];
                float gir = git[row], giz = git[Hh + row], gin = git[2*Hh + row];
                float rr = 1.f/(1.f + __expf(-(gir + ghr)));
                float zz = 1.f/(1.f + __expf(-(giz + ghz)));
                float x  = gin + rr*ghn;
                float ex = __expf(2.f*x);
                float nn = (ex - 1.f)/(ex + 1.f);
                h_stage[row] = (1.f - zz)*nn + zz*h_sh[row];
            }
            __syncthreads();

            // ---- publish h(s+1)+invden(s), tag s+2: 512 threads, 4 copies each ----
            if (tid < Hh) {
                int line = tid & (Hh/2 - 1);
                int c0   = (tid >> 8) * (NCPY/2);
                float ha = last ? 0.f : h_stage[2*line];
                float hb = last ? 0.f : h_stage[2*line + 1];
                float4 pk = make_float4(ha, hb, s_inv, tagf + 1.f);
                #pragma unroll
                for (int c = 0; c < NCPY/2; ++c) stcg4(&g_hT4R[c0 + c][line], pk);
            }

            // ---- off critical path: dout logits, lens, h_sh update ----
            if (wid == 0) {
                dout[s*Vv + lane] = v1;
                if (lane < Vv - 32) dout[s*Vv + lane + 32] = v2;
                if (lane == 0) {
                    if (s_bi == EOSI && mylen == MAXLEN) mylen = s;
                    if (last) dout[MAXLEN*Vv] = (float)mylen;    // lens
                }
            }
            if (!last && tid < Hh) h_sh[tid] = h_stage[tid];
            __syncthreads();   // order h_sh update before next pOutH read
        }
        return;
    }

    // ========================= WORKER BLOCKS =========================
    const int t0   = b * KEYS_PB;
    const int row0 = b * ROWS_PB;
    float e0 = 0.f, e1 = 0.f;

    #define GH_PUBLISH(TAGF)                                                       \
    do {                                                                           \
        if (wid < 12) {                                                            \
            int rl = wid / 3, gate = wid % 3;                                      \
            const float4* wr = (const float4*)(w_hh +                              \
                               (size_t)(gate*Hh + row0 + rl) * Hh);                \
            const float4* hv4g = (const float4*)h_sh;                              \
            float a = 0.f;                                                         \
            _Pragma("unroll")                                                      \
            for (int j = 0; j < 4; ++j) {                                          \
                float4 w = wr[lane + 32*j], h = hv4g[lane + 32*j];                 \
                a = fmaf(w.x, h.x, a); a = fmaf(w.y, h.y, a);                      \
                a = fmaf(w.z, h.z, a); a = fmaf(w.w, h.w, a);                      \
            }                                                                      \
            _Pragma("unroll")                                                      \
            for (int o = 16; o > 0; o >>= 1) a += __shfl_xor_sync(0xffffffffu, a, o); \
            if (lane == 0)                                                         \
                stcg2(&g_ghT[(row0 + rl)*3 + gate], make_float2(a, (TAGF)));       \
        }                                                                          \
    } while (0)

    // ---- prologue: h(-1)=hidden; gh(hidden) in smem; distributed h(0) ----
    if (tid < Hh/4) ((float4*)h_sh)[tid] = ((const float4*)hidden)[tid];
    __syncthreads();
    if (wid < 12) {
        int rl = wid / 3, gate = wid % 3;
        const float4* wr = (const float4*)(w_hh + (size_t)(gate*Hh + row0 + rl) * Hh);
        const float4* hv4g = (const float4*)h_sh;
        float a = 0.f;
        #pragma unroll
        for (int j = 0; j < 4; ++j) {
            float4 w = wr[lane + 32*j], h = hv4g[lane + 32*j];
            a = fmaf(w.x, h.x, a); a = fmaf(w.y, h.y, a);
            a = fmaf(w.z, h.z, a); a = fmaf(w.w, h.w, a);
        }
        #pragma unroll
        for (int o = 16; o > 0; o >>= 1) a += __shfl_xor_sync(0xffffffffu, a, o);
        if (lane == 0) sGH[rl][gate] = a;
    }
    __syncthreads();
    if (wid == 0) {                              // distributed h(0), tag 1
        float hnv = 0.f;
        if (lane < ROWS_PB) {
            int row = row0 + lane;
            const float* git = g_GIT + (size_t)EOSI * (3*Hh);
            float ghr = sGH[lane][0] + b_hh[row];
            float ghz = sGH[lane][1] + b_hh[Hh + row];
            float ghn = sGH[lane][2] + b_hh[2*Hh + row];
            float gir = git[row], giz = git[Hh + row], gin = git[2*Hh + row];
            float rr = 1.f/(1.f + __expf(-(gir + ghr)));
            float zz = 1.f/(1.f + __expf(-(giz + ghz)));
            float x  = gin + rr*ghn;
            float ex = __expf(2.f*x);
            float nn = (ex - 1.f)/(ex + 1.f);
            hnv = (1.f - zz)*nn + zz*h_sh[row];
        }
        float up = __shfl_down_sync(0xffffffffu, hnv, 1);
        if (lane == 0) {
            float4 pk = make_float4(hnv, up, 0.f, 1.f);
            #pragma unroll
            for (int c = 0; c < NCPY; ++c) stcg4(&g_hT4R[c][2*b], pk);
        }
        if (lane == 2) {
            float4 pk = make_float4(hnv, up, 0.f, 1.f);
            #pragma unroll
            for (int c = 0; c < NCPY; ++c) stcg4(&g_hT4R[c][2*b + 1], pk);
        }
    }

    for (int s = 0; s < MAXLEN; ++s) {
        const float tagf = (float)(s + 1);

        // ---- poll h(s)+invden(s-1), done-cached, single target ----
        {
            int done = (tid < Hh/2) ? 0 : 1;
            for (;;) {
                if (!done) {
                    float4 hv = ldcg4(&g_hT4R[b & (NCPY-1)][tid]);
                    if (hv.w >= tagf) {
                        h_sh[2*tid] = hv.x; h_sh[2*tid + 1] = hv.y;
                        if (tid == 0) s_invden = hv.z;
                        done = 1;
                    }
                }
                if (__syncthreads_and(done)) break;
            }
        }

        // capture previous-step weights + invden; store deferred to iteration end
        const float pe0 = e0, pe1 = e1, pinv = s_invden;

        // ---- attention over this block's 64 keys — FIRST (critical path) ----
        {
            const float4* hv4 = (const float4*)h_sh;
            float4 h0 = hv4[lane], h1 = hv4[lane+32], h2 = hv4[lane+64], h3 = hv4[lane+96];
            int ta = t0 + wid, tb = t0 + wid + 32;
            const float4* ka = (const float4*)(enc + (size_t)ta*(DKk+DVv));
            const float4* kb = (const float4*)(enc + (size_t)tb*(DKk+DVv));
            float a0 = 0.f, a1 = 0.f;
            {
                float4 p0 = ka[lane], p1 = ka[lane+32], p2 = ka[lane+64], p3 = ka[lane+96];
                a0 = fmaf(p0.x, h0.x, a0); a0 = fmaf(p0.y, h0.y, a0);
                a0 = fmaf(p0.z, h0.z, a0); a0 = fmaf(p0.w, h0.w, a0);
                a0 = fmaf(p1.x, h1.x, a0); a0 = fmaf(p1.y, h1.y, a0);
                a0 = fmaf(p1.z, h1.z, a0); a0 = fmaf(p1.w, h1.w, a0);
                a0 = fmaf(p2.x, h2.x, a0); a0 = fmaf(p2.y, h2.y, a0);
                a0 = fmaf(p2.z, h2.z, a0); a0 = fmaf(p2.w, h2.w, a0);
                a0 = fmaf(p3.x, h3.x, a0); a0 = fmaf(p3.y, h3.y, a0);
                a0 = fmaf(p3.z, h3.z, a0); a0 = fmaf(p3.w, h3.w, a0);
            }
            {
                float4 q0 = kb[lane], q1 = kb[lane+32], q2 = kb[lane+64], q3 = kb[lane+96];
                a1 = fmaf(q0.x, h0.x, a1); a1 = fmaf(q0.y, h0.y, a1);
                a1 = fmaf(q0.z, h0.z, a1); a1 = fmaf(q0.w, h0.w, a1);
                a1 = fmaf(q1.x, h1.x, a1); a1 = fmaf(q1.y, h1.y, a1);
                a1 = fmaf(q1.z, h1.z, a1); a1 = fmaf(q1.w, h1.w, a1);
                a1 = fmaf(q2.x, h2.x, a1); a1 = fmaf(q2.y, h2.y, a1);
                a1 = fmaf(q2.z, h2.z, a1); a1 = fmaf(q2.w, h2.w, a1);
                a1 = fmaf(q3.x, h3.x, a1); a1 = fmaf(q3.y, h3.y, a1);
                a1 = fmaf(q3.z, h3.z, a1); a1 = fmaf(q3.w, h3.w, a1);
            }
            #pragma unroll
            for (int o = 16; o > 0; o >>= 1) {
                a0 += __shfl_xor_sync(0xffffffffu, a0, o);
                a1 += __shfl_xor_sync(0xffffffffu, a1, o);
            }
            e0 = __expf(a0 * SCALE);
            e1 = __expf(a1 * SCALE);
            float den = e0 + e1;
            float acc0 = e0 * g_WV[(size_t)ta*Vv + lane]
                       + e1 * g_WV[(size_t)tb*Vv + lane];
            float acc1 = 0.f;
            if (lane < Vv - 32)
                acc1 = e0 * g_WV[(size_t)ta*Vv + 32 + lane]
                     + e1 * g_WV[(size_t)tb*Vv + 32 + lane];
            sU[wid][lane] = acc0;
            if (lane < Vv - 32) sU[wid][32 + lane] = acc1;
            if (lane == 0) sDen[wid] = den;
        }
        __syncthreads();

        // ---- publish tagged partials (critical for reducer) ----
        if (tid < Vv) {
            float a = 0.f;
            #pragma unroll
            for (int w = 0; w < 32; ++w) a += sU[w][tid];
            stcg2(&g_pUT[tid*NB + b], make_float2(a, tagf));
        } else if (tid == Vv) {
            float d = 0.f;
            #pragma unroll
            for (int w = 0; w < 32; ++w) d += sDen[w];
            stcg2(&g_pUT[Vv*NB + b], make_float2(d, tagf));
        }

        // ---- gh = w_hh @ h(s): lands during reducer argmax window ----
        if (s < MAXLEN-1) GH_PUBLISH(tagf);

        // ---- deferred: store normalized attention row (s-1) ----
        if (s > 0 && lane == 0) {
            attn[(size_t)(s-1)*TENC + t0 + wid     ] = pe0 * pinv;
            attn[(size_t)(s-1)*TENC + t0 + wid + 32] = pe1 * pinv;
        }
    }

    // ---- tail: poll final invden(199) (tag 201) for last attention row ----
    {
        const float ftag = (float)(MAXLEN + 1);
        int done = (tid == 0) ? 0 : 1;
        for (;;) {
            if (!done) {
                float4 hv = ldcg4(&g_hT4R[b & (NCPY-1)][0]);
                if (hv.w >= ftag) { s_invden = hv.z; done = 1; }
            }
            if (__syncthreads_and(done)) break;
        }
        if (lane == 0) {
            float inv = s_invden;
            attn[(size_t)(MAXLEN-1)*TENC + t0 + wid     ] = e0 * inv;
            attn[(size_t)(MAXLEN-1)*TENC + t0 + wid + 32] = e1 * inv;
        }
    }
}

// ---------------------------------------------------------------------------
extern "C" void kernel_launch(void* const* d_in, const int* in_sizes, int n_in,
                              void* d_out, int out_size)
{
    const float* enc    = (const float*)d_in[0];
    const float* hidden = (const float*)d_in[1];
    const float* embed  = (const float*)d_in[2];
    const float* w_ih   = (const float*)d_in[3];
    const float* w_hh   = (const float*)d_in[4];
    const float* b_ih   = (const float*)d_in[5];
    const float* b_hh   = (const float*)d_in[6];
    const float* w_out  = (const float*)d_in[7];
    const float* b_out  = (const float*)d_in[8];
    float*       out    = (float*)d_out;

    cudaFuncSetAttribute(gi_kernel, cudaFuncAttributeMaxDynamicSharedMemorySize, 81920);
    cudaFuncSetAttribute(wv_kernel, cudaFuncAttributeMaxDynamicSharedMemorySize, 81920);

    reset_kernel<<<1, 1024>>>();
    gi_kernel<<<192, 256, 81920>>>(w_ih, b_ih, embed);
    wv_kernel<<<256, 256, 81920>>>(enc, w_out);
    dec_main<<<NB + 1, TPB>>>(enc, hidden, w_hh, b_hh, w_out, b_out, out);
}